// round 1
// baseline (speedup 1.0000x reference)
#include <cuda_runtime.h>
#include <cuda_bf16.h>
#include <math.h>

// ---------------------------------------------------------------------------
// HeteroAttention: B=4, L=6, X=Y=8, WS=7 (W=49), DIM=256, HEADS=8, DH=32
// Decomposition:
//   K0a pack_qa     : transpose-pack Wq, Wa into [d/4][o][4] layout
//   K0b combine_w   : fold relation_att/msg into per-(b,z) K/V weights+bias
//   K1  q_proj      : Q = (Wq x + bq)*SCALE for l=0 tokens
//   K2  kv_proj     : K' = WKc x + bKc, V' = WVc x + bVc for all (b,z) tokens
//   K3  attn_kernel : per (b,x,y,h): sim -> +bias -> softmax -> out
//   K4  final_proj  : out = Wa attn_out + ba
// ---------------------------------------------------------------------------

#define NBZ   24          // 4*6
#define NBXY  256         // 4*64
#define NKEY  294         // 6*49
#define SCALE 0.17677669529663687f

// scratch (device globals; no allocation allowed)
__device__ float g_WKc[NBZ * 65536];   // packed: bz, d/4, o, d%4
__device__ float g_WVc[NBZ * 65536];
__device__ float g_bKc[NBZ * 256];
__device__ float g_bVc[NBZ * 256];
__device__ float g_WQt[2 * 65536];     // packed per type
__device__ float g_WAt[2 * 65536];
__device__ float g_Kp[2048 * 9408];    // [bxy*8+h][n=z*49+t][p]
__device__ float g_Vp[2048 * 9408];
__device__ float g_Q [2048 * 1568];    // [bxy*8+h][a][p]
__device__ float g_AO[256 * 12544];    // [bxy][a][o]

// ---------------------------------------------------------------- K0a
__global__ void pack_qa(const float* __restrict__ Wq, const float* __restrict__ Wa) {
    int idx = blockIdx.x * 256 + threadIdx.x;       // 0 .. 131071
    int t = idx >> 16;
    int r = idx & 65535;
    int o = r >> 8;
    int d = r & 255;
    int dst = t * 65536 + ((d >> 2) << 10) + (o << 2) + (d & 3);
    g_WQt[dst] = Wq[idx];
    g_WAt[dst] = Wa[idx];
}

// ---------------------------------------------------------------- K0b
__global__ void combine_w(const float* __restrict__ Wk, const float* __restrict__ bk,
                          const float* __restrict__ Wv, const float* __restrict__ bv,
                          const float* __restrict__ ratt, const float* __restrict__ rmsg,
                          const int* __restrict__ mode) {
    __shared__ float att_s[32 * 33];
    __shared__ float msg_s[32 * 33];
    __shared__ float w_s[32 * 256];
    int bz = blockIdx.x >> 3, h = blockIdx.x & 7;
    int b = bz / 6, z = bz - b * 6;
    int t   = mode[b * 6 + z];
    int rel = mode[b * 6] * 2 + t;
    int tid = threadIdx.x;

    for (int i = tid; i < 1024; i += 256) {
        int p = i >> 5, q = i & 31;
        att_s[p * 33 + q] = ratt[((rel * 8 + h) * 32 + p) * 32 + q];
        msg_s[p * 33 + q] = rmsg[((rel * 8 + h) * 32 + p) * 32 + q];
    }
    const float* WkB = Wk + (t * 256 + h * 32) * 256;
    for (int i = tid; i < 8192; i += 256) w_s[i] = WkB[i];
    __syncthreads();

    {   // K side: WKc[o=(h,p)][d] = sum_q att[p][q] * Wk[h*32+q][d]
        int p = tid & 31;
        for (int d = tid >> 5; d < 256; d += 8) {
            float acc = 0.f;
            #pragma unroll
            for (int q = 0; q < 32; q++) acc = fmaf(att_s[p * 33 + q], w_s[q * 256 + d], acc);
            g_WKc[bz * 65536 + ((d >> 2) << 10) + ((h * 32 + p) << 2) + (d & 3)] = acc;
        }
        if (tid < 32) {
            float acc = 0.f;
            #pragma unroll
            for (int q = 0; q < 32; q++) acc = fmaf(att_s[tid * 33 + q], bk[t * 256 + h * 32 + q], acc);
            g_bKc[bz * 256 + h * 32 + tid] = acc;
        }
    }
    __syncthreads();
    const float* WvB = Wv + (t * 256 + h * 32) * 256;
    for (int i = tid; i < 8192; i += 256) w_s[i] = WvB[i];
    __syncthreads();
    {   // V side: WVc[o=(h,qo)][d] = sum_p msg[p][qo] * Wv[h*32+p][d]
        int qo = tid & 31;
        for (int d = tid >> 5; d < 256; d += 8) {
            float acc = 0.f;
            #pragma unroll
            for (int p = 0; p < 32; p++) acc = fmaf(msg_s[p * 33 + qo], w_s[p * 256 + d], acc);
            g_WVc[bz * 65536 + ((d >> 2) << 10) + ((h * 32 + qo) << 2) + (d & 3)] = acc;
        }
        if (tid < 32) {
            float acc = 0.f;
            #pragma unroll
            for (int p = 0; p < 32; p++) acc = fmaf(msg_s[p * 33 + tid], bv[t * 256 + h * 32 + p], acc);
            g_bVc[bz * 256 + h * 32 + tid] = acc;
        }
    }
}

// ---------------------------------------------------------------- shared GEMM core
// 49 tokens x 256 out, K=256.  Wt4 layout: [d/4][o][4]. xs: [t][d] in smem.
__device__ __forceinline__ void gemm49(const float* __restrict__ Wt4,
                                       const float* __restrict__ bias_vec,
                                       const float* xs, float* acc, int o) {
    float bsv = bias_vec[o];
    #pragma unroll
    for (int t = 0; t < 49; t++) acc[t] = bsv;
    const float4* Wp = reinterpret_cast<const float4*>(Wt4) + o;
    const float4* xp = reinterpret_cast<const float4*>(xs);
    for (int c = 0; c < 64; c++) {
        float4 w = Wp[c * 256];
        #pragma unroll
        for (int t = 0; t < 49; t++) {
            float4 xv = xp[t * 64 + c];
            float a = acc[t];
            a = fmaf(w.x, xv.x, a); a = fmaf(w.y, xv.y, a);
            a = fmaf(w.z, xv.z, a); a = fmaf(w.w, xv.w, a);
            acc[t] = a;
        }
    }
}

// ---------------------------------------------------------------- K1: Q projection
__global__ void q_proj(const float* __restrict__ x, const int* __restrict__ mode,
                       const float* __restrict__ bq) {
    extern __shared__ float xs[];
    int bxy = blockIdx.x;                 // 0..255
    int b = bxy >> 6, xy = bxy & 63;
    const float* xsrc = x + ((size_t)(b * 6) * 64 + xy) * 12544;  // l = 0
    for (int i = threadIdx.x; i < 3136; i += 256)
        reinterpret_cast<float4*>(xs)[i] = reinterpret_cast<const float4*>(xsrc)[i];
    __syncthreads();
    int tq = mode[b * 6];
    int o = threadIdx.x;
    float acc[49];
    gemm49(g_WQt + tq * 65536, bq + tq * 256, xs, acc, o);
    int h = o >> 5, p = o & 31;
    float* dst = g_Q + ((size_t)(bxy * 8 + h)) * 1568 + p;
    #pragma unroll
    for (int t = 0; t < 49; t++) dst[t * 32] = acc[t] * SCALE;
}

// ---------------------------------------------------------------- K2: K'/V' projection
__global__ void kv_proj(const float* __restrict__ x) {
    extern __shared__ float xs[];
    int blk = blockIdx.x;                // 0..1535  = bz*64 + xy
    int bz = blk >> 6, xy = blk & 63;
    int b = bz / 6, z = bz - b * 6;
    const float* xsrc = x + (size_t)blk * 12544;
    for (int i = threadIdx.x; i < 3136; i += 256)
        reinterpret_cast<float4*>(xs)[i] = reinterpret_cast<const float4*>(xsrc)[i];
    __syncthreads();
    int bxy = b * 64 + xy;
    int o = threadIdx.x;
    int h = o >> 5, p = o & 31;
    {
        float acc[49];
        gemm49(g_WKc + bz * 65536, g_bKc + bz * 256, xs, acc, o);
        float* dst = g_Kp + ((size_t)(bxy * 8 + h) * NKEY + z * 49) * 32 + p;
        #pragma unroll
        for (int t = 0; t < 49; t++) dst[t * 32] = acc[t];
    }
    {
        float acc[49];
        gemm49(g_WVc + bz * 65536, g_bVc + bz * 256, xs, acc, o);
        float* dst = g_Vp + ((size_t)(bxy * 8 + h) * NKEY + z * 49) * 32 + p;
        #pragma unroll
        for (int t = 0; t < 49; t++) dst[t * 32] = acc[t];
    }
}

// ---------------------------------------------------------------- K3: attention
// grid 2048 = bxy*8 + h. smem: Ks[320][36], Vs[296][32], Qs[49*32], bias[49*49], attnW[8][320]
__global__ void attn_kernel(const float* __restrict__ pos_table) {
    extern __shared__ float sm[];
    float* Ks    = sm;                  // 11520
    float* Vs    = Ks + 11520;          // 9472
    float* Qs    = Vs + 9472;           // 1568
    float* biasS = Qs + 1568;           // 2401
    float* attnW = biasS + 2401;        // 2560
    int bh = blockIdx.x;
    int h = bh & 7, bxy = bh >> 3;
    int tid = threadIdx.x;
    const float* Kg = g_Kp + (size_t)bh * 9408;
    const float* Vg = g_Vp + (size_t)bh * 9408;
    const float* Qg = g_Q  + (size_t)bh * 1568;

    for (int i = tid; i < 10240; i += 256) {
        int n = i >> 5, p = i & 31;
        Ks[n * 36 + p] = (n < NKEY) ? Kg[i] : 0.f;
    }
    for (int i = tid; i < 9472; i += 256) Vs[i] = (i < 9408) ? Vg[i] : 0.f;
    for (int i = tid; i < 1568; i += 256) Qs[i] = Qg[i];
    for (int i = tid; i < 2401; i += 256) {
        int a = i / 49, ef = i - a * 49;
        int au = a / 7, av = a - au * 7, eu = ef / 7, ev = ef - eu * 7;
        int idx = (au - eu + 6) * 13 + (av - ev + 6);
        biasS[i] = pos_table[idx * 8 + h];
    }
    __syncthreads();

    int w = tid >> 5, lane = tid & 31;
    float* aw = attnW + w * 320;
    int qd = lane & 7, ng = lane >> 3;

    for (int a = w; a < 49; a += 8) {
        float4 qv[8];
        const float4* Qrow = reinterpret_cast<const float4*>(Qs + a * 32);
        #pragma unroll
        for (int c = 0; c < 8; c++) qv[c] = Qrow[c];

        float s[10];
        #pragma unroll
        for (int j = 0; j < 10; j++) {
            int n = j * 32 + lane;
            const float4* Krow = reinterpret_cast<const float4*>(Ks + n * 36);
            float acc = 0.f;
            #pragma unroll
            for (int c = 0; c < 8; c++) {
                float4 k4 = Krow[c];
                acc = fmaf(qv[c].x, k4.x, acc); acc = fmaf(qv[c].y, k4.y, acc);
                acc = fmaf(qv[c].z, k4.z, acc); acc = fmaf(qv[c].w, k4.w, acc);
            }
            int zq = n / 49;
            int ef = n - zq * 49;
            s[j] = (n < NKEY) ? (acc + biasS[a * 49 + ef]) : -1e30f;
        }
        // softmax over 294 (warp-distributed)
        float m = s[0];
        #pragma unroll
        for (int j = 1; j < 10; j++) m = fmaxf(m, s[j]);
        #pragma unroll
        for (int off = 16; off; off >>= 1) m = fmaxf(m, __shfl_xor_sync(0xffffffffu, m, off));
        float sum = 0.f;
        #pragma unroll
        for (int j = 0; j < 10; j++) { s[j] = __expf(s[j] - m); sum += s[j]; }
        #pragma unroll
        for (int off = 16; off; off >>= 1) sum += __shfl_xor_sync(0xffffffffu, sum, off);
        float inv = 1.f / sum;
        #pragma unroll
        for (int j = 0; j < 10; j++) aw[j * 32 + lane] = s[j] * inv;
        __syncwarp();

        // out[p] = sum_n attn[n] * V[n][p]; lane -> (quad qd, n-group ng)
        float4 acc4 = make_float4(0.f, 0.f, 0.f, 0.f);
        for (int j = 0; j < 74; j++) {
            int n = j * 4 + ng;
            float av = aw[n];
            float4 v4 = *(reinterpret_cast<const float4*>(Vs + n * 32) + qd);
            acc4.x = fmaf(av, v4.x, acc4.x); acc4.y = fmaf(av, v4.y, acc4.y);
            acc4.z = fmaf(av, v4.z, acc4.z); acc4.w = fmaf(av, v4.w, acc4.w);
        }
        acc4.x += __shfl_xor_sync(0xffffffffu, acc4.x, 8);
        acc4.y += __shfl_xor_sync(0xffffffffu, acc4.y, 8);
        acc4.z += __shfl_xor_sync(0xffffffffu, acc4.z, 8);
        acc4.w += __shfl_xor_sync(0xffffffffu, acc4.w, 8);
        acc4.x += __shfl_xor_sync(0xffffffffu, acc4.x, 16);
        acc4.y += __shfl_xor_sync(0xffffffffu, acc4.y, 16);
        acc4.z += __shfl_xor_sync(0xffffffffu, acc4.z, 16);
        acc4.w += __shfl_xor_sync(0xffffffffu, acc4.w, 16);
        if (ng == 0) {
            float4* dst = reinterpret_cast<float4*>(g_AO + ((size_t)bxy * 49 + a) * 256 + h * 32) + qd;
            *dst = acc4;
        }
        __syncwarp();
    }
}

// ---------------------------------------------------------------- K4: final projection
__global__ void final_proj(const int* __restrict__ mode, const float* __restrict__ ba,
                           float* __restrict__ out) {
    extern __shared__ float xs[];
    int bxy = blockIdx.x;
    int b = bxy >> 6;
    const float* src = g_AO + (size_t)bxy * 12544;
    for (int i = threadIdx.x; i < 3136; i += 256)
        reinterpret_cast<float4*>(xs)[i] = reinterpret_cast<const float4*>(src)[i];
    __syncthreads();
    int ta = mode[b * 6];
    int o = threadIdx.x;
    float acc[49];
    gemm49(g_WAt + ta * 65536, ba + ta * 256, xs, acc, o);
    float* dst = out + (size_t)bxy * 12544 + o;
    #pragma unroll
    for (int t = 0; t < 49; t++) dst[t * 256] = acc[t];
}

// ---------------------------------------------------------------- launch
extern "C" void kernel_launch(void* const* d_in, const int* in_sizes, int n_in,
                              void* d_out, int out_size) {
    const float* x    = (const float*)d_in[0];
    const int*   mode = (const int*)  d_in[1];
    const float* Wq   = (const float*)d_in[2];
    const float* bq   = (const float*)d_in[3];
    const float* Wk   = (const float*)d_in[4];
    const float* bk   = (const float*)d_in[5];
    const float* Wv   = (const float*)d_in[6];
    const float* bv   = (const float*)d_in[7];
    const float* Wa   = (const float*)d_in[8];
    const float* ba   = (const float*)d_in[9];
    const float* ratt = (const float*)d_in[10];
    const float* rmsg = (const float*)d_in[11];
    const float* post = (const float*)d_in[12];
    float* out = (float*)d_out;

    cudaFuncSetAttribute(q_proj,      cudaFuncAttributeMaxDynamicSharedMemorySize, 50176);
    cudaFuncSetAttribute(kv_proj,     cudaFuncAttributeMaxDynamicSharedMemorySize, 50176);
    cudaFuncSetAttribute(final_proj,  cudaFuncAttributeMaxDynamicSharedMemorySize, 50176);
    cudaFuncSetAttribute(attn_kernel, cudaFuncAttributeMaxDynamicSharedMemorySize, 110084);

    pack_qa   <<<512, 256>>>(Wq, Wa);
    combine_w <<<192, 256>>>(Wk, bk, Wv, bv, ratt, rmsg, mode);
    q_proj    <<<256, 256, 50176>>>(x, mode, bq);
    kv_proj   <<<1536, 256, 50176>>>(x);
    attn_kernel<<<2048, 256, 110084>>>(post);
    final_proj<<<256, 256, 50176>>>(mode, ba, out);
}

// round 2
// speedup vs baseline: 1.3303x; 1.3303x over previous
#include <cuda_runtime.h>
#include <cuda_bf16.h>
#include <math.h>

// ---------------------------------------------------------------------------
// HeteroAttention: B=4, L=6, X=Y=8, WS=7 (W=49), DIM=256, HEADS=8, DH=32
// R2: all projection GEMMs on tensor cores (mma.sync m16n8k16 bf16, hi/lo
//     split for fp32-class accuracy). Attention kernel unchanged (fp32).
// ---------------------------------------------------------------------------

#define NKEY  294
#define SCALE 0.17677669529663687f

// ---------------- scratch (device globals; no allocation allowed) ----------
__device__ __nv_bfloat16 g_Xh[19267584];     // x split hi  [bz*3136+t][256]
__device__ __nv_bfloat16 g_Xl[19267584];     // x split lo
__device__ __nv_bfloat16 g_Wkvh[24*512*256]; // combined K/V weights [bz][o][d]
__device__ __nv_bfloat16 g_Wkvl[24*512*256];
__device__ float         g_bKV [24*512];
__device__ __nv_bfloat16 g_WQh[2*65536];
__device__ __nv_bfloat16 g_WQl[2*65536];
__device__ __nv_bfloat16 g_WAh[2*65536];
__device__ __nv_bfloat16 g_WAl[2*65536];
__device__ float g_Kp[2048*9408];            // [bxy*8+h][n=z*49+t][p]
__device__ float g_Vp[2048*9408];
__device__ float g_Q [2048*1568];            // [bxy*8+h][a][p]
__device__ __nv_bfloat16 g_AOh[256*12544];   // attn out split  [bxy][a][o]
__device__ __nv_bfloat16 g_AOl[256*12544];

// ---------------- helpers ---------------------------------------------------
__device__ __forceinline__ unsigned pk(__nv_bfloat16 a, __nv_bfloat16 b) {
    __nv_bfloat162 t = __halves2bfloat162(a, b);
    return *reinterpret_cast<unsigned*>(&t);
}
__device__ __forceinline__ void split4(float4 f, uint2& h, uint2& l) {
    __nv_bfloat16 h0 = __float2bfloat16_rn(f.x), h1 = __float2bfloat16_rn(f.y);
    __nv_bfloat16 h2 = __float2bfloat16_rn(f.z), h3 = __float2bfloat16_rn(f.w);
    __nv_bfloat16 l0 = __float2bfloat16_rn(f.x - __bfloat162float(h0));
    __nv_bfloat16 l1 = __float2bfloat16_rn(f.y - __bfloat162float(h1));
    __nv_bfloat16 l2 = __float2bfloat16_rn(f.z - __bfloat162float(h2));
    __nv_bfloat16 l3 = __float2bfloat16_rn(f.w - __bfloat162float(h3));
    h.x = pk(h0, h1); h.y = pk(h2, h3);
    l.x = pk(l0, l1); l.y = pk(l2, l3);
}
__device__ __forceinline__ unsigned lds2(const __nv_bfloat16* s, int idx) {
    return *reinterpret_cast<const unsigned*>(s + idx);
}
__device__ __forceinline__ void mma_bf16(float* c, unsigned a0, unsigned a1,
                                         unsigned a2, unsigned a3,
                                         unsigned b0, unsigned b1) {
    asm volatile(
        "mma.sync.aligned.m16n8k16.row.col.f32.bf16.bf16.f32 "
        "{%0,%1,%2,%3}, {%4,%5,%6,%7}, {%8,%9}, {%0,%1,%2,%3};\n"
        : "+f"(c[0]), "+f"(c[1]), "+f"(c[2]), "+f"(c[3])
        : "r"(a0), "r"(a1), "r"(a2), "r"(a3), "r"(b0), "r"(b1));
}

// ---------------- pack kernels ----------------------------------------------
__global__ void pack_x(const float4* __restrict__ x) {
    int i = blockIdx.x * 256 + threadIdx.x;       // 4,816,896 float4 exactly
    float4 f = x[i];
    uint2 h, l; split4(f, h, l);
    reinterpret_cast<uint2*>(g_Xh)[i] = h;
    reinterpret_cast<uint2*>(g_Xl)[i] = l;
}

__global__ void pack_qa(const float* __restrict__ Wq, const float* __restrict__ Wa) {
    int i = blockIdx.x * 256 + threadIdx.x;       // 32768 float4
    uint2 h, l;
    float4 fq = reinterpret_cast<const float4*>(Wq)[i];
    split4(fq, h, l);
    reinterpret_cast<uint2*>(g_WQh)[i] = h;
    reinterpret_cast<uint2*>(g_WQl)[i] = l;
    float4 fa = reinterpret_cast<const float4*>(Wa)[i];
    split4(fa, h, l);
    reinterpret_cast<uint2*>(g_WAh)[i] = h;
    reinterpret_cast<uint2*>(g_WAl)[i] = l;
}

// ---------------- K0b: fold relation matrices into K/V weights -------------
__global__ void combine_w(const float* __restrict__ Wk, const float* __restrict__ bk,
                          const float* __restrict__ Wv, const float* __restrict__ bv,
                          const float* __restrict__ ratt, const float* __restrict__ rmsg,
                          const int* __restrict__ mode) {
    __shared__ float att_s[32 * 33];
    __shared__ float msg_s[32 * 33];
    __shared__ float w_s[32 * 256];
    int bz = blockIdx.x >> 3, h = blockIdx.x & 7;
    int b = bz / 6, z = bz - b * 6;
    int t   = mode[b * 6 + z];
    int rel = mode[b * 6] * 2 + t;
    int tid = threadIdx.x;

    for (int i = tid; i < 1024; i += 256) {
        int p = i >> 5, q = i & 31;
        att_s[p * 33 + q] = ratt[((rel * 8 + h) * 32 + p) * 32 + q];
        msg_s[p * 33 + q] = rmsg[((rel * 8 + h) * 32 + p) * 32 + q];
    }
    const float* WkB = Wk + (t * 256 + h * 32) * 256;
    for (int i = tid; i < 8192; i += 256) w_s[i] = WkB[i];
    __syncthreads();

    {   // K: WKc[(h,p)][d] = sum_q att[p][q] * Wk[h*32+q][d]
        int p = tid & 31;
        for (int d = tid >> 5; d < 256; d += 8) {
            float acc = 0.f;
            #pragma unroll
            for (int q = 0; q < 32; q++) acc = fmaf(att_s[p * 33 + q], w_s[q * 256 + d], acc);
            size_t idx = (size_t)bz * 131072 + (size_t)(h * 32 + p) * 256 + d;
            __nv_bfloat16 hv = __float2bfloat16_rn(acc);
            g_Wkvh[idx] = hv;
            g_Wkvl[idx] = __float2bfloat16_rn(acc - __bfloat162float(hv));
        }
        if (tid < 32) {
            float acc = 0.f;
            #pragma unroll
            for (int q = 0; q < 32; q++) acc = fmaf(att_s[tid * 33 + q], bk[t * 256 + h * 32 + q], acc);
            g_bKV[bz * 512 + h * 32 + tid] = acc;
        }
    }
    __syncthreads();
    const float* WvB = Wv + (t * 256 + h * 32) * 256;
    for (int i = tid; i < 8192; i += 256) w_s[i] = WvB[i];
    __syncthreads();
    {   // V: WVc[(h,qo)][d] = sum_p msg[p][qo] * Wv[h*32+p][d]
        int qo = tid & 31;
        for (int d = tid >> 5; d < 256; d += 8) {
            float acc = 0.f;
            #pragma unroll
            for (int p = 0; p < 32; p++) acc = fmaf(msg_s[p * 33 + qo], w_s[p * 256 + d], acc);
            size_t idx = (size_t)bz * 131072 + (size_t)(256 + h * 32 + qo) * 256 + d;
            __nv_bfloat16 hv = __float2bfloat16_rn(acc);
            g_Wkvh[idx] = hv;
            g_Wkvl[idx] = __float2bfloat16_rn(acc - __bfloat162float(hv));
        }
        if (tid < 32) {
            float acc = 0.f;
            #pragma unroll
            for (int p = 0; p < 32; p++) acc = fmaf(msg_s[p * 33 + tid], bv[t * 256 + h * 32 + p], acc);
            g_bKV[bz * 512 + 256 + h * 32 + tid] = acc;
        }
    }
}

// ---------------- tensor-core 64x64x256 tile (bf16 hi/lo split) -------------
// Block = 128 threads (4 warps). Warp w owns rows [w*16, w*16+16), all 64 cols.
// smem layout: [64 rows][40 halves] (stride 40 -> conflict-free frag loads).
__device__ __forceinline__ void gemm64(
    const __nv_bfloat16* __restrict__ Ah, const __nv_bfloat16* __restrict__ Al,
    const __nv_bfloat16* __restrict__ Bh, const __nv_bfloat16* __restrict__ Bl,
    float acc[8][4])
{
    __shared__ __align__(16) __nv_bfloat16 sAh[2560], sAl[2560], sBh[2560], sBl[2560];
    int tid  = threadIdx.x;
    int row2 = tid >> 1;            // 0..63
    int seg  = (tid & 1) * 2;       // 0 or 2

    const uint4* uAh = reinterpret_cast<const uint4*>(Ah);
    const uint4* uAl = reinterpret_cast<const uint4*>(Al);
    const uint4* uBh = reinterpret_cast<const uint4*>(Bh);
    const uint4* uBl = reinterpret_cast<const uint4*>(Bl);
    uint4* s4Ah = reinterpret_cast<uint4*>(sAh);
    uint4* s4Al = reinterpret_cast<uint4*>(sAl);
    uint4* s4Bh = reinterpret_cast<uint4*>(sBh);
    uint4* s4Bl = reinterpret_cast<uint4*>(sBl);

    int warp = tid >> 5, lane = tid & 31;
    int gid = lane >> 2, tg = lane & 3;
    int ar0 = (warp * 16 + gid) * 40 + 2 * tg;       // A frag base (rows)
    int ar1 = ar0 + 8 * 40;

    uint4 rAh0, rAh1, rAl0, rAl1, rBh0, rBh1, rBl0, rBl1;
    int gbase = row2 * 32 + seg;                     // uint4 units, +k0/8 per chunk
    int sbase = row2 * 5 + seg;

    // prologue: chunk 0
    {
        rAh0 = uAh[gbase]; rAh1 = uAh[gbase + 1];
        rAl0 = uAl[gbase]; rAl1 = uAl[gbase + 1];
        rBh0 = uBh[gbase]; rBh1 = uBh[gbase + 1];
        rBl0 = uBl[gbase]; rBl1 = uBl[gbase + 1];
    }
    s4Ah[sbase] = rAh0; s4Ah[sbase + 1] = rAh1;
    s4Al[sbase] = rAl0; s4Al[sbase + 1] = rAl1;
    s4Bh[sbase] = rBh0; s4Bh[sbase + 1] = rBh1;
    s4Bl[sbase] = rBl0; s4Bl[sbase + 1] = rBl1;
    __syncthreads();

    #pragma unroll 1
    for (int ch = 0; ch < 8; ch++) {
        if (ch < 7) {
            int g = gbase + (ch + 1) * 4;
            rAh0 = uAh[g]; rAh1 = uAh[g + 1];
            rAl0 = uAl[g]; rAl1 = uAl[g + 1];
            rBh0 = uBh[g]; rBh1 = uBh[g + 1];
            rBl0 = uBl[g]; rBl1 = uBl[g + 1];
        }
        #pragma unroll
        for (int ks = 0; ks < 32; ks += 16) {
            unsigned ah0 = lds2(sAh, ar0 + ks);
            unsigned ah1 = lds2(sAh, ar1 + ks);
            unsigned ah2 = lds2(sAh, ar0 + ks + 8);
            unsigned ah3 = lds2(sAh, ar1 + ks + 8);
            unsigned al0 = lds2(sAl, ar0 + ks);
            unsigned al1 = lds2(sAl, ar1 + ks);
            unsigned al2 = lds2(sAl, ar0 + ks + 8);
            unsigned al3 = lds2(sAl, ar1 + ks + 8);
            #pragma unroll
            for (int j = 0; j < 8; j++) {
                int br = (j * 8 + gid) * 40 + 2 * tg + ks;
                unsigned bh0 = lds2(sBh, br);
                unsigned bh1 = lds2(sBh, br + 8);
                unsigned bl0 = lds2(sBl, br);
                unsigned bl1 = lds2(sBl, br + 8);
                mma_bf16(acc[j], ah0, ah1, ah2, ah3, bh0, bh1);
                mma_bf16(acc[j], ah0, ah1, ah2, ah3, bl0, bl1);
                mma_bf16(acc[j], al0, al1, al2, al3, bh0, bh1);
            }
        }
        __syncthreads();
        if (ch < 7) {
            s4Ah[sbase] = rAh0; s4Ah[sbase + 1] = rAh1;
            s4Al[sbase] = rAl0; s4Al[sbase + 1] = rAl1;
            s4Bh[sbase] = rBh0; s4Bh[sbase + 1] = rBh1;
            s4Bl[sbase] = rBl0; s4Bl[sbase + 1] = rBl1;
            __syncthreads();
        }
    }
}

// ---------------- K1: Q projection ------------------------------------------
__global__ void __launch_bounds__(128) q_mma(const int* __restrict__ mode,
                                             const float* __restrict__ bq) {
    int blk = blockIdx.x;                  // b*196 + mt*4 + nt
    int b = blk / 196; int r = blk - b * 196;
    int mt = r >> 2, nt = r & 3;
    int tq = mode[b * 6];
    size_t aoff = (size_t)(b * 6 * 3136 + mt * 64) * 256;
    size_t boff = (size_t)tq * 65536 + (size_t)nt * 64 * 256;
    float acc[8][4] = {};
    gemm64(g_Xh + aoff, g_Xl + aoff, g_WQh + boff, g_WQl + boff, acc);

    int warp = threadIdx.x >> 5, lane = threadIdx.x & 31;
    int gid = lane >> 2, tg = lane & 3;
    #pragma unroll
    for (int j = 0; j < 8; j++) {
        #pragma unroll
        for (int e = 0; e < 4; e++) {
            int row = mt * 64 + warp * 16 + gid + ((e >> 1) << 3);
            int o = nt * 64 + j * 8 + tg * 2 + (e & 1);
            float v = (acc[j][e] + bq[tq * 256 + o]) * SCALE;
            int xy = row / 49, a = row - xy * 49;
            int h = o >> 5, p = o & 31;
            g_Q[((size_t)((b * 64 + xy) * 8 + h)) * 1568 + a * 32 + p] = v;
        }
    }
}

// ---------------- K2: K'/V' projection --------------------------------------
__global__ void __launch_bounds__(128) kv_mma() {
    int blk = blockIdx.x;                  // bz*392 + mt*8 + nt
    int bz = blk / 392; int r = blk - bz * 392;
    int mt = r >> 3, nt = r & 7;
    int b = bz / 6, z = bz - b * 6;
    size_t aoff = (size_t)(bz * 3136 + mt * 64) * 256;
    size_t boff = (size_t)bz * 131072 + (size_t)nt * 64 * 256;
    float acc[8][4] = {};
    gemm64(g_Xh + aoff, g_Xl + aoff, g_Wkvh + boff, g_Wkvl + boff, acc);

    int warp = threadIdx.x >> 5, lane = threadIdx.x & 31;
    int gid = lane >> 2, tg = lane & 3;
    float* dst = (nt < 4) ? g_Kp : g_Vp;
    #pragma unroll
    for (int j = 0; j < 8; j++) {
        #pragma unroll
        for (int e = 0; e < 4; e++) {
            int row = mt * 64 + warp * 16 + gid + ((e >> 1) << 3);
            int o = nt * 64 + j * 8 + tg * 2 + (e & 1);
            float v = acc[j][e] + g_bKV[bz * 512 + o];
            int od = o & 255;
            int xy = row / 49, ef = row - xy * 49;
            int h = od >> 5, p = od & 31;
            dst[((size_t)(((b * 64 + xy) * 8 + h)) * NKEY + z * 49 + ef) * 32 + p] = v;
        }
    }
}

// ---------------- K3: attention (fp32, unchanged core) ----------------------
__global__ void attn_kernel(const float* __restrict__ pos_table) {
    extern __shared__ float sm[];
    float* Ks    = sm;                  // 320*36
    float* Vs    = Ks + 11520;          // 296*32
    float* Qs    = Vs + 9472;           // 49*32
    float* biasS = Qs + 1568;           // 49*49
    float* attnW = biasS + 2401;        // 8*320
    int bh = blockIdx.x;
    int h = bh & 7, bxy = bh >> 3;
    int tid = threadIdx.x;
    const float* Kg = g_Kp + (size_t)bh * 9408;
    const float* Vg = g_Vp + (size_t)bh * 9408;
    const float* Qg = g_Q  + (size_t)bh * 1568;

    for (int i = tid; i < 10240; i += 256) {
        int n = i >> 5, p = i & 31;
        Ks[n * 36 + p] = (n < NKEY) ? Kg[i] : 0.f;
    }
    for (int i = tid; i < 9472; i += 256) Vs[i] = (i < 9408) ? Vg[i] : 0.f;
    for (int i = tid; i < 1568; i += 256) Qs[i] = Qg[i];
    for (int i = tid; i < 2401; i += 256) {
        int a = i / 49, ef = i - a * 49;
        int au = a / 7, av = a - au * 7, eu = ef / 7, ev = ef - eu * 7;
        int idx = (au - eu + 6) * 13 + (av - ev + 6);
        biasS[i] = pos_table[idx * 8 + h];
    }
    __syncthreads();

    int w = tid >> 5, lane = tid & 31;
    float* aw = attnW + w * 320;
    int qd = lane & 7, ng = lane >> 3;

    for (int a = w; a < 49; a += 8) {
        float4 qv[8];
        const float4* Qrow = reinterpret_cast<const float4*>(Qs + a * 32);
        #pragma unroll
        for (int c = 0; c < 8; c++) qv[c] = Qrow[c];

        float s[10];
        #pragma unroll
        for (int j = 0; j < 10; j++) {
            int n = j * 32 + lane;
            const float4* Krow = reinterpret_cast<const float4*>(Ks + n * 36);
            float acc = 0.f;
            #pragma unroll
            for (int c = 0; c < 8; c++) {
                float4 k4 = Krow[c];
                acc = fmaf(qv[c].x, k4.x, acc); acc = fmaf(qv[c].y, k4.y, acc);
                acc = fmaf(qv[c].z, k4.z, acc); acc = fmaf(qv[c].w, k4.w, acc);
            }
            int zq = n / 49;
            int ef = n - zq * 49;
            s[j] = (n < NKEY) ? (acc + biasS[a * 49 + ef]) : -1e30f;
        }
        float m = s[0];
        #pragma unroll
        for (int j = 1; j < 10; j++) m = fmaxf(m, s[j]);
        #pragma unroll
        for (int off = 16; off; off >>= 1) m = fmaxf(m, __shfl_xor_sync(0xffffffffu, m, off));
        float sum = 0.f;
        #pragma unroll
        for (int j = 0; j < 10; j++) { s[j] = __expf(s[j] - m); sum += s[j]; }
        #pragma unroll
        for (int off = 16; off; off >>= 1) sum += __shfl_xor_sync(0xffffffffu, sum, off);
        float inv = 1.f / sum;
        #pragma unroll
        for (int j = 0; j < 10; j++) aw[j * 32 + lane] = s[j] * inv;
        __syncwarp();

        float4 acc4 = make_float4(0.f, 0.f, 0.f, 0.f);
        for (int j = 0; j < 74; j++) {
            int n = j * 4 + ng;
            float av = aw[n];
            float4 v4 = *(reinterpret_cast<const float4*>(Vs + n * 32) + qd);
            acc4.x = fmaf(av, v4.x, acc4.x); acc4.y = fmaf(av, v4.y, acc4.y);
            acc4.z = fmaf(av, v4.z, acc4.z); acc4.w = fmaf(av, v4.w, acc4.w);
        }
        acc4.x += __shfl_xor_sync(0xffffffffu, acc4.x, 8);
        acc4.y += __shfl_xor_sync(0xffffffffu, acc4.y, 8);
        acc4.z += __shfl_xor_sync(0xffffffffu, acc4.z, 8);
        acc4.w += __shfl_xor_sync(0xffffffffu, acc4.w, 8);
        acc4.x += __shfl_xor_sync(0xffffffffu, acc4.x, 16);
        acc4.y += __shfl_xor_sync(0xffffffffu, acc4.y, 16);
        acc4.z += __shfl_xor_sync(0xffffffffu, acc4.z, 16);
        acc4.w += __shfl_xor_sync(0xffffffffu, acc4.w, 16);
        if (ng == 0) {
            int base = (bxy * 49 + a) * 256 + h * 32 + qd * 4;
            uint2 hv, lv; split4(acc4, hv, lv);
            *reinterpret_cast<uint2*>(g_AOh + base) = hv;
            *reinterpret_cast<uint2*>(g_AOl + base) = lv;
        }
        __syncwarp();
    }
}

// ---------------- K4: final projection --------------------------------------
__global__ void __launch_bounds__(128) ao_mma(const int* __restrict__ mode,
                                              const float* __restrict__ ba,
                                              float* __restrict__ out) {
    int blk = blockIdx.x;                  // b*196 + mt*4 + nt
    int b = blk / 196; int r = blk - b * 196;
    int mt = r >> 2, nt = r & 3;
    int ta = mode[b * 6];
    size_t aoff = (size_t)(b * 3136 + mt * 64) * 256;
    size_t boff = (size_t)ta * 65536 + (size_t)nt * 64 * 256;
    float acc[8][4] = {};
    gemm64(g_AOh + aoff, g_AOl + aoff, g_WAh + boff, g_WAl + boff, acc);

    int warp = threadIdx.x >> 5, lane = threadIdx.x & 31;
    int gid = lane >> 2, tg = lane & 3;
    #pragma unroll
    for (int j = 0; j < 8; j++) {
        #pragma unroll
        for (int e = 0; e < 4; e++) {
            int row = mt * 64 + warp * 16 + gid + ((e >> 1) << 3);
            int o = nt * 64 + j * 8 + tg * 2 + (e & 1);
            out[(size_t)(b * 3136 + row) * 256 + o] = acc[j][e] + ba[ta * 256 + o];
        }
    }
}

// ---------------- launch -----------------------------------------------------
extern "C" void kernel_launch(void* const* d_in, const int* in_sizes, int n_in,
                              void* d_out, int out_size) {
    const float* x    = (const float*)d_in[0];
    const int*   mode = (const int*)  d_in[1];
    const float* Wq   = (const float*)d_in[2];
    const float* bq   = (const float*)d_in[3];
    const float* Wk   = (const float*)d_in[4];
    const float* bk   = (const float*)d_in[5];
    const float* Wv   = (const float*)d_in[6];
    const float* bv   = (const float*)d_in[7];
    const float* Wa   = (const float*)d_in[8];
    const float* ba   = (const float*)d_in[9];
    const float* ratt = (const float*)d_in[10];
    const float* rmsg = (const float*)d_in[11];
    const float* post = (const float*)d_in[12];
    float* out = (float*)d_out;

    cudaFuncSetAttribute(attn_kernel, cudaFuncAttributeMaxDynamicSharedMemorySize, 110084);

    pack_x    <<<18816, 256>>>(reinterpret_cast<const float4*>(x));
    pack_qa   <<<128, 256>>>(Wq, Wa);
    combine_w <<<192, 256>>>(Wk, bk, Wv, bv, ratt, rmsg, mode);
    q_mma     <<<784, 128>>>(mode, bq);
    kv_mma    <<<9408, 128>>>();
    attn_kernel<<<2048, 256, 110084>>>(post);
    ao_mma    <<<784, 128>>>(mode, ba, out);
}

// round 3
// speedup vs baseline: 1.6324x; 1.2270x over previous
#include <cuda_runtime.h>
#include <cuda_bf16.h>
#include <math.h>

// ---------------------------------------------------------------------------
// HeteroAttention R3: ldmatrix + cp.async double-buffered bf16 hi/lo GEMMs.
// B=4, L=6, X=Y=8, W=49, DIM=256, HEADS=8, DH=32
// ---------------------------------------------------------------------------

#define NKEY  294
#define SCALE 0.17677669529663687f

// ---------------- scratch ----------------------------------------------------
__device__ __nv_bfloat16 g_Xh[19267584];     // [bz*3136+t][256]
__device__ __nv_bfloat16 g_Xl[19267584];
__device__ __nv_bfloat16 g_Wkvh[24*512*256]; // [bz][o(512)][d]
__device__ __nv_bfloat16 g_Wkvl[24*512*256];
__device__ float         g_bKV [24*512];
__device__ __nv_bfloat16 g_WQh[2*65536];
__device__ __nv_bfloat16 g_WQl[2*65536];
__device__ __nv_bfloat16 g_WAh[2*65536];
__device__ __nv_bfloat16 g_WAl[2*65536];
__device__ float g_Kp[2048*9408];            // [bxy*8+h][n][p]
__device__ float g_Vp[2048*9408];
__device__ float g_Q [2048*1568];            // [bxy*8+h][a][p]
__device__ __nv_bfloat16 g_AOh[256*12544];
__device__ __nv_bfloat16 g_AOl[256*12544];

// ---------------- helpers -----------------------------------------------------
__device__ __forceinline__ unsigned pk(__nv_bfloat16 a, __nv_bfloat16 b) {
    __nv_bfloat162 t = __halves2bfloat162(a, b);
    return *reinterpret_cast<unsigned*>(&t);
}
__device__ __forceinline__ void split4(float4 f, uint2& h, uint2& l) {
    __nv_bfloat16 h0 = __float2bfloat16_rn(f.x), h1 = __float2bfloat16_rn(f.y);
    __nv_bfloat16 h2 = __float2bfloat16_rn(f.z), h3 = __float2bfloat16_rn(f.w);
    __nv_bfloat16 l0 = __float2bfloat16_rn(f.x - __bfloat162float(h0));
    __nv_bfloat16 l1 = __float2bfloat16_rn(f.y - __bfloat162float(h1));
    __nv_bfloat16 l2 = __float2bfloat16_rn(f.z - __bfloat162float(h2));
    __nv_bfloat16 l3 = __float2bfloat16_rn(f.w - __bfloat162float(h3));
    h.x = pk(h0, h1); h.y = pk(h2, h3);
    l.x = pk(l0, l1); l.y = pk(l2, l3);
}
__device__ __forceinline__ void mma_bf16(float* c, unsigned a0, unsigned a1,
                                         unsigned a2, unsigned a3,
                                         unsigned b0, unsigned b1) {
    asm volatile(
        "mma.sync.aligned.m16n8k16.row.col.f32.bf16.bf16.f32 "
        "{%0,%1,%2,%3}, {%4,%5,%6,%7}, {%8,%9}, {%0,%1,%2,%3};\n"
        : "+f"(c[0]), "+f"(c[1]), "+f"(c[2]), "+f"(c[3])
        : "r"(a0), "r"(a1), "r"(a2), "r"(a3), "r"(b0), "r"(b1));
}
__device__ __forceinline__ void ldsm4(unsigned& r0, unsigned& r1,
                                      unsigned& r2, unsigned& r3, const void* p) {
    unsigned a = (unsigned)__cvta_generic_to_shared(p);
    asm volatile("ldmatrix.sync.aligned.m8n8.x4.shared.b16 {%0,%1,%2,%3}, [%4];\n"
                 : "=r"(r0), "=r"(r1), "=r"(r2), "=r"(r3) : "r"(a));
}
__device__ __forceinline__ void cpa16(void* dst, const void* src) {
    unsigned d = (unsigned)__cvta_generic_to_shared(dst);
    asm volatile("cp.async.cg.shared.global [%0], [%1], 16;\n" :: "r"(d), "l"(src));
}
__device__ __forceinline__ void cpa_commit() { asm volatile("cp.async.commit_group;\n"); }

// ---------------- pack kernels ------------------------------------------------
__global__ void pack_x(const float4* __restrict__ x) {
    int i = blockIdx.x * 256 + threadIdx.x;
    float4 f = x[i];
    uint2 h, l; split4(f, h, l);
    reinterpret_cast<uint2*>(g_Xh)[i] = h;
    reinterpret_cast<uint2*>(g_Xl)[i] = l;
}
__global__ void pack_qa(const float* __restrict__ Wq, const float* __restrict__ Wa) {
    int i = blockIdx.x * 256 + threadIdx.x;
    uint2 h, l;
    float4 fq = reinterpret_cast<const float4*>(Wq)[i];
    split4(fq, h, l);
    reinterpret_cast<uint2*>(g_WQh)[i] = h;
    reinterpret_cast<uint2*>(g_WQl)[i] = l;
    float4 fa = reinterpret_cast<const float4*>(Wa)[i];
    split4(fa, h, l);
    reinterpret_cast<uint2*>(g_WAh)[i] = h;
    reinterpret_cast<uint2*>(g_WAl)[i] = l;
}

// ---------------- K0b: fold relation matrices --------------------------------
__global__ void combine_w(const float* __restrict__ Wk, const float* __restrict__ bk,
                          const float* __restrict__ Wv, const float* __restrict__ bv,
                          const float* __restrict__ ratt, const float* __restrict__ rmsg,
                          const int* __restrict__ mode) {
    __shared__ float att_s[32 * 33];
    __shared__ float msg_s[32 * 33];
    __shared__ float w_s[32 * 256];
    int bz = blockIdx.x >> 3, h = blockIdx.x & 7;
    int b = bz / 6, z = bz - b * 6;
    int t   = mode[b * 6 + z];
    int rel = mode[b * 6] * 2 + t;
    int tid = threadIdx.x;

    for (int i = tid; i < 1024; i += 256) {
        int p = i >> 5, q = i & 31;
        att_s[p * 33 + q] = ratt[((rel * 8 + h) * 32 + p) * 32 + q];
        msg_s[p * 33 + q] = rmsg[((rel * 8 + h) * 32 + p) * 32 + q];
    }
    const float* WkB = Wk + (t * 256 + h * 32) * 256;
    for (int i = tid; i < 8192; i += 256) w_s[i] = WkB[i];
    __syncthreads();
    {
        int p = tid & 31;
        for (int d = tid >> 5; d < 256; d += 8) {
            float acc = 0.f;
            #pragma unroll
            for (int q = 0; q < 32; q++) acc = fmaf(att_s[p * 33 + q], w_s[q * 256 + d], acc);
            size_t idx = (size_t)bz * 131072 + (size_t)(h * 32 + p) * 256 + d;
            __nv_bfloat16 hv = __float2bfloat16_rn(acc);
            g_Wkvh[idx] = hv;
            g_Wkvl[idx] = __float2bfloat16_rn(acc - __bfloat162float(hv));
        }
        if (tid < 32) {
            float acc = 0.f;
            #pragma unroll
            for (int q = 0; q < 32; q++) acc = fmaf(att_s[tid * 33 + q], bk[t * 256 + h * 32 + q], acc);
            g_bKV[bz * 512 + h * 32 + tid] = acc;
        }
    }
    __syncthreads();
    const float* WvB = Wv + (t * 256 + h * 32) * 256;
    for (int i = tid; i < 8192; i += 256) w_s[i] = WvB[i];
    __syncthreads();
    {
        int qo = tid & 31;
        for (int d = tid >> 5; d < 256; d += 8) {
            float acc = 0.f;
            #pragma unroll
            for (int p = 0; p < 32; p++) acc = fmaf(msg_s[p * 33 + qo], w_s[p * 256 + d], acc);
            size_t idx = (size_t)bz * 131072 + (size_t)(256 + h * 32 + qo) * 256 + d;
            __nv_bfloat16 hv = __float2bfloat16_rn(acc);
            g_Wkvh[idx] = hv;
            g_Wkvl[idx] = __float2bfloat16_rn(acc - __bfloat162float(hv));
        }
        if (tid < 32) {
            float acc = 0.f;
            #pragma unroll
            for (int p = 0; p < 32; p++) acc = fmaf(msg_s[p * 33 + tid], bv[t * 256 + h * 32 + p], acc);
            g_bKV[bz * 512 + 256 + h * 32 + tid] = acc;
        }
    }
}

// ---------------- 64x128x256 tensor-core tile ---------------------------------
// 256 threads = 8 warps: warp_m = warp>>1 (0..3, m16 each), warp_n = warp&1 (n64).
// smem rows padded to 40 halves (80B stride -> conflict-free ldmatrix).
// chunks of K=32, double-buffered cp.async.
// smem bytes: sAh 2*5120, sAl 2*5120, sBh 2*10240, sBl 2*10240 = 61440.
__device__ __forceinline__ void load_chunk(char* sm, int buf,
        const __nv_bfloat16* __restrict__ Ah, const __nv_bfloat16* __restrict__ Al,
        const __nv_bfloat16* __restrict__ Bh, const __nv_bfloat16* __restrict__ Bl,
        int kc) {
    int tid = threadIdx.x;
    {   // A: 64 rows x 4 segs, hi+lo
        int r = tid >> 2, seg = tid & 3;
        int so = (r * 40 + seg * 8) * 2;
        const __nv_bfloat16* s = Ah + r * 256 + kc + seg * 8;
        cpa16(sm + buf * 5120 + so, s);
        cpa16(sm + 10240 + buf * 5120 + so, Al + r * 256 + kc + seg * 8);
    }
    #pragma unroll
    for (int i = 0; i < 2; i++) {   // B: 128 rows x 4 segs, hi+lo
        int id = tid + i * 256;
        int r = id >> 2, seg = id & 3;
        int so = (r * 40 + seg * 8) * 2;
        cpa16(sm + 20480 + buf * 10240 + so, Bh + r * 256 + kc + seg * 8);
        cpa16(sm + 40960 + buf * 10240 + so, Bl + r * 256 + kc + seg * 8);
    }
}

__device__ __forceinline__ void gemm_tile(
        const __nv_bfloat16* __restrict__ Ah, const __nv_bfloat16* __restrict__ Al,
        const __nv_bfloat16* __restrict__ Bh, const __nv_bfloat16* __restrict__ Bl,
        float acc[8][4], char* sm) {
    int tid = threadIdx.x;
    int warp = tid >> 5, lane = tid & 31;
    int wm = warp >> 1, wn = warp & 1;
    int lrow = lane & 15, lcol8 = (lane >> 4) << 3;

    load_chunk(sm, 0, Ah, Al, Bh, Bl, 0);
    cpa_commit();

    #pragma unroll 1
    for (int ch = 0; ch < 8; ch++) {
        if (ch < 7) {
            load_chunk(sm, (ch + 1) & 1, Ah, Al, Bh, Bl, (ch + 1) * 32);
            cpa_commit();
            asm volatile("cp.async.wait_group 1;\n");
        } else {
            asm volatile("cp.async.wait_group 0;\n");
        }
        __syncthreads();
        int buf = ch & 1;
        const __nv_bfloat16* pAh = (const __nv_bfloat16*)(sm + buf * 5120);
        const __nv_bfloat16* pAl = (const __nv_bfloat16*)(sm + 10240 + buf * 5120);
        const __nv_bfloat16* pBh = (const __nv_bfloat16*)(sm + 20480 + buf * 10240);
        const __nv_bfloat16* pBl = (const __nv_bfloat16*)(sm + 40960 + buf * 10240);
        #pragma unroll
        for (int ks = 0; ks < 32; ks += 16) {
            unsigned ah0, ah1, ah2, ah3, al0, al1, al2, al3;
            const __nv_bfloat16* ap = pAh + (wm * 16 + lrow) * 40 + ks + lcol8;
            ldsm4(ah0, ah1, ah2, ah3, ap);
            ldsm4(al0, al1, al2, al3, pAl + (wm * 16 + lrow) * 40 + ks + lcol8);
            #pragma unroll
            for (int t = 0; t < 4; t++) {
                unsigned bh0, bh1, bh2, bh3, bl0, bl1, bl2, bl3;
                int boff = (wn * 64 + t * 16 + lrow) * 40 + ks + lcol8;
                ldsm4(bh0, bh1, bh2, bh3, pBh + boff);
                ldsm4(bl0, bl1, bl2, bl3, pBl + boff);
                mma_bf16(acc[2 * t],     ah0, ah1, ah2, ah3, bh0, bh2);
                mma_bf16(acc[2 * t],     ah0, ah1, ah2, ah3, bl0, bl2);
                mma_bf16(acc[2 * t],     al0, al1, al2, al3, bh0, bh2);
                mma_bf16(acc[2 * t + 1], ah0, ah1, ah2, ah3, bh1, bh3);
                mma_bf16(acc[2 * t + 1], ah0, ah1, ah2, ah3, bl1, bl3);
                mma_bf16(acc[2 * t + 1], al0, al1, al2, al3, bh1, bh3);
            }
        }
        __syncthreads();
    }
}

// ---------------- K2: K'/V' projection ----------------------------------------
__global__ void __launch_bounds__(256) kv_mma() {
    extern __shared__ char sm[];
    int blk = blockIdx.x;                 // bz*196 + mt*4 + nt
    int bz = blk / 196; int r = blk - bz * 196;
    int mt = r >> 2, nt = r & 3;
    int b = bz / 6, z = bz - b * 6;
    const __nv_bfloat16* Ah = g_Xh + (size_t)(bz * 3136 + mt * 64) * 256;
    const __nv_bfloat16* Al = g_Xl + (size_t)(bz * 3136 + mt * 64) * 256;
    const __nv_bfloat16* Bh = g_Wkvh + (size_t)bz * 131072 + (size_t)nt * 128 * 256;
    const __nv_bfloat16* Bl = g_Wkvl + (size_t)bz * 131072 + (size_t)nt * 128 * 256;
    float acc[8][4] = {};
    gemm_tile(Ah, Al, Bh, Bl, acc, sm);

    int warp = threadIdx.x >> 5, lane = threadIdx.x & 31;
    int wm = warp >> 1, wn = warp & 1;
    int gid = lane >> 2, tg = lane & 3;
    #pragma unroll
    for (int j = 0; j < 8; j++) {
        #pragma unroll
        for (int e = 0; e < 4; e++) {
            int row = mt * 64 + wm * 16 + gid + ((e >> 1) << 3);
            int o = nt * 128 + wn * 64 + j * 8 + tg * 2 + (e & 1);
            float v = acc[j][e] + g_bKV[bz * 512 + o];
            float* dst = (o < 256) ? g_Kp : g_Vp;
            int od = o & 255;
            int xy = row / 49, ef = row - xy * 49;
            int h = od >> 5, p = od & 31;
            dst[((size_t)(((b * 64 + xy) * 8 + h)) * NKEY + z * 49 + ef) * 32 + p] = v;
        }
    }
}

// ---------------- K1: Q projection --------------------------------------------
__global__ void __launch_bounds__(256) q_mma(const int* __restrict__ mode,
                                             const float* __restrict__ bq) {
    extern __shared__ char sm[];
    int blk = blockIdx.x;                 // b*98 + mt*2 + nt
    int b = blk / 98; int r = blk - b * 98;
    int mt = r >> 1, nt = r & 1;
    int tq = mode[b * 6];
    const __nv_bfloat16* Ah = g_Xh + (size_t)(b * 6 * 3136 + mt * 64) * 256;
    const __nv_bfloat16* Al = g_Xl + (size_t)(b * 6 * 3136 + mt * 64) * 256;
    const __nv_bfloat16* Bh = g_WQh + (size_t)tq * 65536 + (size_t)nt * 128 * 256;
    const __nv_bfloat16* Bl = g_WQl + (size_t)tq * 65536 + (size_t)nt * 128 * 256;
    float acc[8][4] = {};
    gemm_tile(Ah, Al, Bh, Bl, acc, sm);

    int warp = threadIdx.x >> 5, lane = threadIdx.x & 31;
    int wm = warp >> 1, wn = warp & 1;
    int gid = lane >> 2, tg = lane & 3;
    #pragma unroll
    for (int j = 0; j < 8; j++) {
        #pragma unroll
        for (int e = 0; e < 4; e++) {
            int row = mt * 64 + wm * 16 + gid + ((e >> 1) << 3);
            int o = nt * 128 + wn * 64 + j * 8 + tg * 2 + (e & 1);
            float v = (acc[j][e] + bq[tq * 256 + o]) * SCALE;
            int xy = row / 49, a = row - xy * 49;
            int h = o >> 5, p = o & 31;
            g_Q[((size_t)((b * 64 + xy) * 8 + h)) * 1568 + a * 32 + p] = v;
        }
    }
}

// ---------------- K3: attention (unchanged) ------------------------------------
__global__ void attn_kernel(const float* __restrict__ pos_table) {
    extern __shared__ float smf[];
    float* Ks    = smf;
    float* Vs    = Ks + 11520;
    float* Qs    = Vs + 9472;
    float* biasS = Qs + 1568;
    float* attnW = biasS + 2401;
    int bh = blockIdx.x;
    int h = bh & 7, bxy = bh >> 3;
    int tid = threadIdx.x;
    const float* Kg = g_Kp + (size_t)bh * 9408;
    const float* Vg = g_Vp + (size_t)bh * 9408;
    const float* Qg = g_Q  + (size_t)bh * 1568;

    for (int i = tid; i < 10240; i += 256) {
        int n = i >> 5, p = i & 31;
        Ks[n * 36 + p] = (n < NKEY) ? Kg[i] : 0.f;
    }
    for (int i = tid; i < 9472; i += 256) Vs[i] = (i < 9408) ? Vg[i] : 0.f;
    for (int i = tid; i < 1568; i += 256) Qs[i] = Qg[i];
    for (int i = tid; i < 2401; i += 256) {
        int a = i / 49, ef = i - a * 49;
        int au = a / 7, av = a - au * 7, eu = ef / 7, ev = ef - eu * 7;
        int idx = (au - eu + 6) * 13 + (av - ev + 6);
        biasS[i] = pos_table[idx * 8 + h];
    }
    __syncthreads();

    int w = tid >> 5, lane = tid & 31;
    float* aw = attnW + w * 320;
    int qd = lane & 7, ng = lane >> 3;

    for (int a = w; a < 49; a += 8) {
        float4 qv[8];
        const float4* Qrow = reinterpret_cast<const float4*>(Qs + a * 32);
        #pragma unroll
        for (int c = 0; c < 8; c++) qv[c] = Qrow[c];

        float s[10];
        #pragma unroll
        for (int j = 0; j < 10; j++) {
            int n = j * 32 + lane;
            const float4* Krow = reinterpret_cast<const float4*>(Ks + n * 36);
            float acc = 0.f;
            #pragma unroll
            for (int c = 0; c < 8; c++) {
                float4 k4 = Krow[c];
                acc = fmaf(qv[c].x, k4.x, acc); acc = fmaf(qv[c].y, k4.y, acc);
                acc = fmaf(qv[c].z, k4.z, acc); acc = fmaf(qv[c].w, k4.w, acc);
            }
            int zq = n / 49;
            int ef = n - zq * 49;
            s[j] = (n < NKEY) ? (acc + biasS[a * 49 + ef]) : -1e30f;
        }
        float m = s[0];
        #pragma unroll
        for (int j = 1; j < 10; j++) m = fmaxf(m, s[j]);
        #pragma unroll
        for (int off = 16; off; off >>= 1) m = fmaxf(m, __shfl_xor_sync(0xffffffffu, m, off));
        float sum = 0.f;
        #pragma unroll
        for (int j = 0; j < 10; j++) { s[j] = __expf(s[j] - m); sum += s[j]; }
        #pragma unroll
        for (int off = 16; off; off >>= 1) sum += __shfl_xor_sync(0xffffffffu, sum, off);
        float inv = 1.f / sum;
        #pragma unroll
        for (int j = 0; j < 10; j++) aw[j * 32 + lane] = s[j] * inv;
        __syncwarp();

        float4 acc4 = make_float4(0.f, 0.f, 0.f, 0.f);
        for (int j = 0; j < 74; j++) {
            int n = j * 4 + ng;
            float av = aw[n];
            float4 v4 = *(reinterpret_cast<const float4*>(Vs + n * 32) + qd);
            acc4.x = fmaf(av, v4.x, acc4.x); acc4.y = fmaf(av, v4.y, acc4.y);
            acc4.z = fmaf(av, v4.z, acc4.z); acc4.w = fmaf(av, v4.w, acc4.w);
        }
        acc4.x += __shfl_xor_sync(0xffffffffu, acc4.x, 8);
        acc4.y += __shfl_xor_sync(0xffffffffu, acc4.y, 8);
        acc4.z += __shfl_xor_sync(0xffffffffu, acc4.z, 8);
        acc4.w += __shfl_xor_sync(0xffffffffu, acc4.w, 8);
        acc4.x += __shfl_xor_sync(0xffffffffu, acc4.x, 16);
        acc4.y += __shfl_xor_sync(0xffffffffu, acc4.y, 16);
        acc4.z += __shfl_xor_sync(0xffffffffu, acc4.z, 16);
        acc4.w += __shfl_xor_sync(0xffffffffu, acc4.w, 16);
        if (ng == 0) {
            int base = (bxy * 49 + a) * 256 + h * 32 + qd * 4;
            uint2 hv, lv; split4(acc4, hv, lv);
            *reinterpret_cast<uint2*>(g_AOh + base) = hv;
            *reinterpret_cast<uint2*>(g_AOl + base) = lv;
        }
        __syncwarp();
    }
}

// ---------------- K4: final projection -----------------------------------------
__global__ void __launch_bounds__(256) ao_mma(const int* __restrict__ mode,
                                              const float* __restrict__ ba,
                                              float* __restrict__ out) {
    extern __shared__ char sm[];
    int blk = blockIdx.x;                 // b*98 + mt*2 + nt
    int b = blk / 98; int r = blk - b * 98;
    int mt = r >> 1, nt = r & 1;
    int ta = mode[b * 6];
    const __nv_bfloat16* Ah = g_AOh + (size_t)(b * 3136 + mt * 64) * 256;
    const __nv_bfloat16* Al = g_AOl + (size_t)(b * 3136 + mt * 64) * 256;
    const __nv_bfloat16* Bh = g_WAh + (size_t)ta * 65536 + (size_t)nt * 128 * 256;
    const __nv_bfloat16* Bl = g_WAl + (size_t)ta * 65536 + (size_t)nt * 128 * 256;
    float acc[8][4] = {};
    gemm_tile(Ah, Al, Bh, Bl, acc, sm);

    int warp = threadIdx.x >> 5, lane = threadIdx.x & 31;
    int wm = warp >> 1, wn = warp & 1;
    int gid = lane >> 2, tg = lane & 3;
    #pragma unroll
    for (int j = 0; j < 8; j++) {
        #pragma unroll
        for (int e = 0; e < 4; e++) {
            int row = mt * 64 + wm * 16 + gid + ((e >> 1) << 3);
            int o = nt * 128 + wn * 64 + j * 8 + tg * 2 + (e & 1);
            out[(size_t)(b * 3136 + row) * 256 + o] = acc[j][e] + ba[ta * 256 + o];
        }
    }
}

// ---------------- launch --------------------------------------------------------
extern "C" void kernel_launch(void* const* d_in, const int* in_sizes, int n_in,
                              void* d_out, int out_size) {
    const float* x    = (const float*)d_in[0];
    const int*   mode = (const int*)  d_in[1];
    const float* Wq   = (const float*)d_in[2];
    const float* bq   = (const float*)d_in[3];
    const float* Wk   = (const float*)d_in[4];
    const float* bk   = (const float*)d_in[5];
    const float* Wv   = (const float*)d_in[6];
    const float* bv   = (const float*)d_in[7];
    const float* Wa   = (const float*)d_in[8];
    const float* ba   = (const float*)d_in[9];
    const float* ratt = (const float*)d_in[10];
    const float* rmsg = (const float*)d_in[11];
    const float* post = (const float*)d_in[12];
    float* out = (float*)d_out;

    cudaFuncSetAttribute(attn_kernel, cudaFuncAttributeMaxDynamicSharedMemorySize, 110084);
    cudaFuncSetAttribute(kv_mma, cudaFuncAttributeMaxDynamicSharedMemorySize, 61440);
    cudaFuncSetAttribute(q_mma,  cudaFuncAttributeMaxDynamicSharedMemorySize, 61440);
    cudaFuncSetAttribute(ao_mma, cudaFuncAttributeMaxDynamicSharedMemorySize, 61440);

    pack_x    <<<18816, 256>>>(reinterpret_cast<const float4*>(x));
    pack_qa   <<<128, 256>>>(Wq, Wa);
    combine_w <<<192, 256>>>(Wk, bk, Wv, bv, ratt, rmsg, mode);
    q_mma     <<<392, 256, 61440>>>(mode, bq);
    kv_mma    <<<4704, 256, 61440>>>();
    attn_kernel<<<2048, 256, 110084>>>(post);
    ao_mma    <<<392, 256, 61440>>>(mode, ba, out);
}